// round 10
// baseline (speedup 1.0000x reference)
#include <cuda_runtime.h>
#include <cuda_bf16.h>
#include <math.h>
#include <stdint.h>

#define B_  2
#define T_  1024
#define C_  4096
#define H_  32
#define G_  8
#define D_  128
#define M_  (B_*T_)          // 2048 rows

// ---------------- scratch (__device__ globals; no allocs allowed) ----------
__device__ __nv_bfloat16 g_xh [M_ * C_];
__device__ __nv_bfloat16 g_xl [M_ * C_];
__device__ __nv_bfloat16 g_ath[M_ * C_];
__device__ __nv_bfloat16 g_atl[M_ * C_];
__device__ __nv_bfloat16 g_qh [M_ * H_ * D_];
__device__ __nv_bfloat16 g_ql [M_ * H_ * D_];
__device__ __nv_bfloat16 g_kh [M_ * G_ * D_];
__device__ __nv_bfloat16 g_kl [M_ * G_ * D_];
__device__ __nv_bfloat16 g_vh [M_ * G_ * D_];
__device__ __nv_bfloat16 g_vl [M_ * G_ * D_];
// transposed weights, [N, K] K-major, bf16 hi/lo
__device__ __nv_bfloat16 g_wqh[(H_*D_) * C_];
__device__ __nv_bfloat16 g_wql[(H_*D_) * C_];
__device__ __nv_bfloat16 g_wkh[(G_*D_) * C_];
__device__ __nv_bfloat16 g_wkl[(G_*D_) * C_];
__device__ __nv_bfloat16 g_wvh[(G_*D_) * C_];
__device__ __nv_bfloat16 g_wvl[(G_*D_) * C_];
__device__ __nv_bfloat16 g_woh[C_ * (H_*D_)];
__device__ __nv_bfloat16 g_wol[C_ * (H_*D_)];

// ---------------- helpers ---------------------------------------------------
__device__ __forceinline__ uint32_t smem_u32(const void* p) {
    uint32_t a;
    asm("{ .reg .u64 t; cvta.to.shared.u64 t, %1; cvt.u32.u64 %0, t; }"
        : "=r"(a) : "l"(p));
    return a;
}
__device__ __forceinline__ void cp16(uint32_t dst, const void* src) {
    asm volatile("cp.async.cg.shared.global [%0], [%1], 16;"
                 :: "r"(dst), "l"(src) : "memory");
}
__device__ __forceinline__ void cp_commit() {
    asm volatile("cp.async.commit_group;" ::: "memory");
}
template <int N>
__device__ __forceinline__ void cp_wait() {
    asm volatile("cp.async.wait_group %0;" :: "n"(N) : "memory");
}
__device__ __forceinline__ void mma_bf16(float* c, const uint32_t* a, const uint32_t* b) {
    asm volatile(
        "mma.sync.aligned.m16n8k16.row.col.f32.bf16.bf16.f32 "
        "{%0,%1,%2,%3}, {%4,%5,%6,%7}, {%8,%9}, {%0,%1,%2,%3};"
        : "+f"(c[0]), "+f"(c[1]), "+f"(c[2]), "+f"(c[3])
        : "r"(a[0]), "r"(a[1]), "r"(a[2]), "r"(a[3]), "r"(b[0]), "r"(b[1]));
}
__device__ __forceinline__ void ldsm4(uint32_t* r, uint32_t a) {
    asm volatile("ldmatrix.sync.aligned.m8n8.x4.shared.b16 {%0,%1,%2,%3}, [%4];"
        : "=r"(r[0]), "=r"(r[1]), "=r"(r[2]), "=r"(r[3]) : "r"(a));
}
__device__ __forceinline__ void ldsm4t(uint32_t* r, uint32_t a) {
    asm volatile("ldmatrix.sync.aligned.m8n8.x4.trans.shared.b16 {%0,%1,%2,%3}, [%4];"
        : "=r"(r[0]), "=r"(r[1]), "=r"(r[2]), "=r"(r[3]) : "r"(a));
}
__device__ __forceinline__ uint32_t packbf(float a, float b) {
    __nv_bfloat162 t;
    t.x = __float2bfloat16(a);
    t.y = __float2bfloat16(b);
    return *(uint32_t*)&t;
}

// ---------------- GEMM tile config: 256(M) x 128(N), BK=32 -----------------
#define SA 40                              // padded row stride (bf16) = 80 B
#define A_MAT (256 * SA * 2)               // 20480 B per A matrix (hi or lo)
#define B_MAT (128 * SA * 2)               // 10240 B per B matrix
#define STAGE_BYTES (2 * A_MAT + 2 * B_MAT)   // 61440
#define GEMM_SMEM (2 * STAGE_BYTES)           // 122880

// Mainloop shared between the two GEMM kernels, expanded inline.
#define GEMM_MAINLOOP(ACC)                                                     \
    issue_stage(0, 0);                                                         \
    for (int c = 0; c < nchunks; ++c) {                                        \
        const int st = c & 1;                                                  \
        if (c + 1 < nchunks) { issue_stage(c + 1, st ^ 1); cp_wait<1>(); }     \
        else                 { cp_wait<0>(); }                                 \
        __syncthreads();                                                       \
        const uint32_t sAh = smb + st * STAGE_BYTES;                           \
        const uint32_t sAl = sAh + A_MAT;                                      \
        const uint32_t sBh = sAh + 2 * A_MAT;                                  \
        const uint32_t sBl = sBh + B_MAT;                                      \
        _Pragma("unroll")                                                      \
        for (int k16 = 0; k16 < 32; k16 += 16) {                               \
            uint32_t ah[4][4], al[4][4];                                       \
            _Pragma("unroll")                                                  \
            for (int mt = 0; mt < 4; mt++) {                                   \
                const uint32_t ao = aoff0 + mt * 16 * (SA * 2) + k16 * 2;      \
                ldsm4(ah[mt], sAh + ao);                                       \
                ldsm4(al[mt], sAl + ao);                                       \
            }                                                                  \
            _Pragma("unroll")                                                  \
            for (int nt2 = 0; nt2 < 4; nt2++) {                                \
                const uint32_t bo = boff0 + nt2 * 16 * (SA * 2) + k16 * 2;     \
                uint32_t bh4[4], bl4[4];                                       \
                ldsm4(bh4, sBh + bo);                                          \
                ldsm4(bl4, sBl + bo);                                          \
                uint32_t bhe[2] = { bh4[0], bh4[2] }, bho[2] = { bh4[1], bh4[3] }; \
                uint32_t ble[2] = { bl4[0], bl4[2] }, blo[2] = { bl4[1], bl4[3] }; \
                _Pragma("unroll")                                              \
                for (int mt = 0; mt < 4; mt++) {                               \
                    mma_bf16(ACC[mt][2 * nt2],     ah[mt], bhe);               \
                    mma_bf16(ACC[mt][2 * nt2],     ah[mt], ble);               \
                    mma_bf16(ACC[mt][2 * nt2],     al[mt], bhe);               \
                    mma_bf16(ACC[mt][2 * nt2 + 1], ah[mt], bho);               \
                    mma_bf16(ACC[mt][2 * nt2 + 1], ah[mt], blo);               \
                    mma_bf16(ACC[mt][2 * nt2 + 1], al[mt], bho);               \
                }                                                              \
            }                                                                  \
        }                                                                      \
        __syncthreads();                                                       \
    }

// per-stage cp.async: 3072 16B chunks, 12 per thread
#define GEMM_ISSUE_STAGE_BODY                                                  \
    const int k0 = c << 5;                                                     \
    _Pragma("unroll")                                                          \
    for (int j = 0; j < 12; j++) {                                             \
        const int id = tid + (j << 8);                                         \
        int grow; uint32_t base; const __nv_bfloat16* gp; int r;               \
        if (id < 2048) {                                                       \
            const int mat = id >> 10, idx = id & 1023;                         \
            r = idx >> 2; grow = m0 + r;                                       \
            base = (uint32_t)(mat * A_MAT);                                    \
            gp = mat ? Alp : Ahp;                                              \
        } else {                                                               \
            const int id2 = id - 2048;                                         \
            const int mat = id2 >> 9, idx = id2 & 511;                         \
            r = idx >> 2; grow = n0 + r;                                       \
            base = (uint32_t)(2 * A_MAT + mat * B_MAT);                        \
            gp = mat ? Blp : Bhp;                                              \
        }                                                                      \
        const int s = id & 3;                                                  \
        const __nv_bfloat16* src = gp + (size_t)grow * Kdim + k0 + s * 8;      \
        cp16(smb + st * STAGE_BYTES + base + r * (SA * 2) + s * 16, src);      \
    }                                                                          \
    cp_commit();

// ---------------------------------------------------------------------------
// Fused QKV projection GEMM (256x128 tiles) + RoPE/scale/split epilogue.
// grid.x in [0,48): [0,32) Q, [32,40) K, [40,48) V; grid.y = M/256.
// ---------------------------------------------------------------------------
__global__ __launch_bounds__(256, 1)
void qkv_gemm_kernel(const __nv_bfloat16* __restrict__ xh_, const __nv_bfloat16* __restrict__ xl_,
                     const __nv_bfloat16* __restrict__ wqh_, const __nv_bfloat16* __restrict__ wql_,
                     const __nv_bfloat16* __restrict__ wkh_, const __nv_bfloat16* __restrict__ wkl_,
                     const __nv_bfloat16* __restrict__ wvh_, const __nv_bfloat16* __restrict__ wvl_,
                     __nv_bfloat16* __restrict__ qh_, __nv_bfloat16* __restrict__ ql_,
                     __nv_bfloat16* __restrict__ kh_, __nv_bfloat16* __restrict__ kl_,
                     __nv_bfloat16* __restrict__ vh_, __nv_bfloat16* __restrict__ vl_)
{
    extern __shared__ char sm[];
    const uint32_t smb = smem_u32(sm);
    const int tid  = threadIdx.x;
    const int lane = tid & 31;
    const int w    = tid >> 5;
    const int wm   = w & 3;            // 4 m-slices of 64
    const int wn   = w >> 2;           // 2 n-slices of 64
    const int gg   = lane >> 2;
    const int tt   = lane & 3;
    const int m0   = blockIdx.y * 256;
    const int bx   = blockIdx.x;

    const __nv_bfloat16 *Bhp, *Blp;
    __nv_bfloat16 *OH, *OL;
    int n0, Nmat, rope;
    float scale;
    if (bx < 32)      { Bhp = wqh_; Blp = wql_; OH = qh_; OL = ql_; n0 = bx * 128;        Nmat = H_ * D_; rope = 1; scale = 0.08838834764831845f; }
    else if (bx < 40) { Bhp = wkh_; Blp = wkl_; OH = kh_; OL = kl_; n0 = (bx - 32) * 128; Nmat = G_ * D_; rope = 1; scale = 1.f; }
    else              { Bhp = wvh_; Blp = wvl_; OH = vh_; OL = vl_; n0 = (bx - 40) * 128; Nmat = G_ * D_; rope = 0; scale = 1.f; }

    const __nv_bfloat16* Ahp = xh_;
    const __nv_bfloat16* Alp = xl_;
    const int Kdim = C_;
    const int nchunks = Kdim >> 5;

    auto issue_stage = [&](int c, int st) { GEMM_ISSUE_STAGE_BODY };

    float acc[4][8][4];
#pragma unroll
    for (int i = 0; i < 4; i++)
#pragma unroll
        for (int j = 0; j < 8; j++)
#pragma unroll
            for (int l = 0; l < 4; l++) acc[i][j][l] = 0.f;

    const uint32_t aoff0 = (uint32_t)((wm * 64 + (lane & 7) + ((lane >> 3) & 1) * 8) * (SA * 2)
                                      + ((lane >> 4) & 1) * 16);
    const uint32_t boff0 = (uint32_t)((wn * 64 + (lane & 7) + ((lane >> 3) & 1) * 8) * (SA * 2)
                                      + ((lane >> 4) & 1) * 16);

    GEMM_MAINLOOP(acc)

    // ---- fused epilogue: RoPE + scale + bf16 hi/lo split ----
#pragma unroll
    for (int mt = 0; mt < 4; mt++) {
#pragma unroll
        for (int nt = 0; nt < 8; nt++) {
            const int row = m0 + wm * 64 + mt * 16 + gg;       // row, row+8
            const int col = n0 + wn * 64 + nt * 8 + 2 * tt;    // even -> RoPE pair
            float a0 = acc[mt][nt][0], a1 = acc[mt][nt][1];
            float a2 = acc[mt][nt][2], a3 = acc[mt][nt][3];
            if (rope) {
                const int d2 = (col & 127) >> 1;
                const float invf = powf(10000.0f, -(float)d2 / 64.0f);
                float s0, c0, s1, c1;
                sincosf((float)(row & (T_ - 1)) * invf, &s0, &c0);
                sincosf((float)((row + 8) & (T_ - 1)) * invf, &s1, &c1);
                const float r0 = (a0 * c0 - a1 * s0) * scale;
                const float i0 = (a0 * s0 + a1 * c0) * scale;
                const float r1 = (a2 * c1 - a3 * s1) * scale;
                const float i1 = (a2 * s1 + a3 * c1) * scale;
                a0 = r0; a1 = i0; a2 = r1; a3 = i1;
            }
            const float h0 = __bfloat162float(__float2bfloat16(a0));
            const float h1 = __bfloat162float(__float2bfloat16(a1));
            const float h2 = __bfloat162float(__float2bfloat16(a2));
            const float h3 = __bfloat162float(__float2bfloat16(a3));
            const size_t o0 = (size_t)row * Nmat + col;
            const size_t o1 = (size_t)(row + 8) * Nmat + col;
            *(uint32_t*)(OH + o0) = packbf(h0, h1);
            *(uint32_t*)(OH + o1) = packbf(h2, h3);
            *(uint32_t*)(OL + o0) = packbf(a0 - h0, a1 - h1);
            *(uint32_t*)(OL + o1) = packbf(a2 - h2, a3 - h3);
        }
    }
}

// ---------------------------------------------------------------------------
// O-projection GEMM (256x128 tiles), fp32 out + bias.
// ---------------------------------------------------------------------------
__global__ __launch_bounds__(256, 1)
void gemm_mma_kernel(const __nv_bfloat16* __restrict__ Ahp, const __nv_bfloat16* __restrict__ Alp,
                     const __nv_bfloat16* __restrict__ Bhp, const __nv_bfloat16* __restrict__ Blp,
                     const float* __restrict__ bias, float* __restrict__ Cm,
                     int Ndim, int Kdim)
{
    extern __shared__ char sm[];
    const uint32_t smb = smem_u32(sm);
    const int tid  = threadIdx.x;
    const int lane = tid & 31;
    const int w    = tid >> 5;
    const int wm   = w & 3;
    const int wn   = w >> 2;
    const int gg   = lane >> 2;
    const int tt   = lane & 3;
    const int m0   = blockIdx.y * 256;
    const int n0   = blockIdx.x * 128;

    const int nchunks = Kdim >> 5;

    auto issue_stage = [&](int c, int st) { GEMM_ISSUE_STAGE_BODY };

    float acc[4][8][4];
#pragma unroll
    for (int i = 0; i < 4; i++)
#pragma unroll
        for (int j = 0; j < 8; j++)
#pragma unroll
            for (int l = 0; l < 4; l++) acc[i][j][l] = 0.f;

    const uint32_t aoff0 = (uint32_t)((wm * 64 + (lane & 7) + ((lane >> 3) & 1) * 8) * (SA * 2)
                                      + ((lane >> 4) & 1) * 16);
    const uint32_t boff0 = (uint32_t)((wn * 64 + (lane & 7) + ((lane >> 3) & 1) * 8) * (SA * 2)
                                      + ((lane >> 4) & 1) * 16);

    GEMM_MAINLOOP(acc)

#pragma unroll
    for (int mt = 0; mt < 4; mt++) {
#pragma unroll
        for (int nt = 0; nt < 8; nt++) {
            const int row = m0 + wm * 64 + mt * 16 + gg;
            const int col = n0 + wn * 64 + nt * 8 + 2 * tt;
            float2 v0 = make_float2(acc[mt][nt][0] + bias[col], acc[mt][nt][1] + bias[col + 1]);
            float2 v1 = make_float2(acc[mt][nt][2] + bias[col], acc[mt][nt][3] + bias[col + 1]);
            *(float2*)(Cm + (size_t)row * Ndim + col)       = v0;
            *(float2*)(Cm + (size_t)(row + 8) * Ndim + col) = v1;
        }
    }
}

// ---------------- fp32 -> bf16 hi/lo split ---------------------------------
__global__ void split_kernel(const float* __restrict__ src,
                             __nv_bfloat16* __restrict__ hi,
                             __nv_bfloat16* __restrict__ lo, int n)
{
    int i = blockIdx.x * blockDim.x + threadIdx.x;
    if (i >= n) return;
    float a = src[i];
    __nv_bfloat16 h = __float2bfloat16(a);
    hi[i] = h;
    lo[i] = __float2bfloat16(a - __bfloat162float(h));
}

// ---------------------------------------------------------------------------
// Merged transpose+split of all 4 weight matrices (flat 1D tile grid).
// ---------------------------------------------------------------------------
__global__ void transpose_split_all_kernel(
    const float* __restrict__ Wq, const float* __restrict__ Wk,
    const float* __restrict__ Wv, const float* __restrict__ Wo,
    __nv_bfloat16* __restrict__ wqh, __nv_bfloat16* __restrict__ wql,
    __nv_bfloat16* __restrict__ wkh, __nv_bfloat16* __restrict__ wkl,
    __nv_bfloat16* __restrict__ wvh, __nv_bfloat16* __restrict__ wvl,
    __nv_bfloat16* __restrict__ woh, __nv_bfloat16* __restrict__ wol)
{
    __shared__ float t[32][33];
    const int tile = blockIdx.x;
    const float* W;
    __nv_bfloat16 *Th, *Tl;
    int Kd, Nd, l;
    if (tile < 16384)      { W = Wq; Th = wqh; Tl = wql; Kd = C_;      Nd = H_ * D_; l = tile; }
    else if (tile < 20480) { W = Wk; Th = wkh; Tl = wkl; Kd = C_;      Nd = G_ * D_; l = tile - 16384; }
    else if (tile < 24576) { W = Wv; Th = wvh; Tl = wvl; Kd = C_;      Nd = G_ * D_; l = tile - 20480; }
    else                   { W = Wo; Th = woh; Tl = wol; Kd = H_ * D_; Nd = C_;      l = tile - 24576; }
    const int nx = Nd >> 5;
    const int n0 = (l % nx) * 32, k0 = (l / nx) * 32;
    const int tx = threadIdx.x, ty = threadIdx.y;
#pragma unroll
    for (int j = 0; j < 32; j += 8)
        t[ty + j][tx] = W[(size_t)(k0 + ty + j) * Nd + n0 + tx];
    __syncthreads();
#pragma unroll
    for (int j = 0; j < 32; j += 8) {
        float a = t[tx][ty + j];
        __nv_bfloat16 h = __float2bfloat16(a);
        size_t o = (size_t)(n0 + ty + j) * Kd + k0 + tx;
        Th[o] = h;
        Tl[o] = __float2bfloat16(a - __bfloat162float(h));
    }
}

// ---------------------------------------------------------------------------
// Flash attention, bf16x3 HMMA (unchanged from R6/R8).
// ---------------------------------------------------------------------------
#define FA_ROW 272
#define FA_MAT (64 * FA_ROW)
#define FA_SMEM (6 * FA_MAT)

__global__ __launch_bounds__(128, 2)
void flash_attn_kernel(const __nv_bfloat16* __restrict__ qh, const __nv_bfloat16* __restrict__ ql,
                       const __nv_bfloat16* __restrict__ kh, const __nv_bfloat16* __restrict__ kl,
                       const __nv_bfloat16* __restrict__ vh, const __nv_bfloat16* __restrict__ vl,
                       __nv_bfloat16* __restrict__ oh, __nv_bfloat16* __restrict__ ol)
{
    extern __shared__ char sm[];
    const uint32_t smb = smem_u32(sm);
    const uint32_t sQh = smb,            sQl = smb + FA_MAT;
    const uint32_t sKh = smb + 2*FA_MAT, sKl = smb + 3*FA_MAT;
    const uint32_t sVh = smb + 4*FA_MAT, sVl = smb + 5*FA_MAT;
    const int tid = threadIdx.x, lane = tid & 31, w = tid >> 5;
    const int gg = lane >> 2, tt = lane & 3;
    const int tq = blockIdx.x, h = blockIdx.y, b = blockIdx.z, g = h >> 2;
    const int qbase = tq * 64;

    const uint32_t lrow = (lane & 7) + ((lane >> 3) & 1) * 8;
    const uint32_t lcol16 = ((lane >> 4) & 1) * 16;

#pragma unroll
    for (int j = 0; j < 16; j++) {
        const int i = tid + j * 128;
        const int matlo = i >> 10, idx = i & 1023, r = idx >> 4, s = idx & 15;
        const __nv_bfloat16* src = (matlo ? ql : qh)
            + (((size_t)b * T_ + qbase + r) * H_ + h) * D_ + s * 8;
        cp16((matlo ? sQl : sQh) + r * FA_ROW + s * 16, src);
    }
    cp_commit();

    auto loadK = [&](int s0) {
#pragma unroll
        for (int j = 0; j < 16; j++) {
            const int i = tid + j * 128;
            const int matlo = i >> 10, idx = i & 1023, r = idx >> 4, s = idx & 15;
            const __nv_bfloat16* src = (matlo ? kl : kh)
                + (((size_t)b * T_ + s0 + r) * G_ + g) * D_ + s * 8;
            cp16((matlo ? sKl : sKh) + r * FA_ROW + s * 16, src);
        }
        cp_commit();
    };
    auto loadV = [&](int s0) {
#pragma unroll
        for (int j = 0; j < 16; j++) {
            const int i = tid + j * 128;
            const int matlo = i >> 10, idx = i & 1023, r = idx >> 4, s = idx & 15;
            const __nv_bfloat16* src = (matlo ? vl : vh)
                + (((size_t)b * T_ + s0 + r) * G_ + g) * D_ + s * 8;
            cp16((matlo ? sVl : sVh) + r * FA_ROW + s * 16, src);
        }
        cp_commit();
    };

    loadK(0);
    loadV(0);
    cp_wait<1>();
    __syncthreads();

    uint32_t qfh[8][4], qfl[8][4];
    const uint32_t qoff = (w * 16 + lrow) * FA_ROW + lcol16;
#pragma unroll
    for (int k16 = 0; k16 < 8; k16++) {
        ldsm4(qfh[k16], sQh + qoff + k16 * 32);
        ldsm4(qfl[k16], sQl + qoff + k16 * 32);
    }

    float O[16][4];
#pragma unroll
    for (int i = 0; i < 16; i++)
#pragma unroll
        for (int j = 0; j < 4; j++) O[i][j] = 0.f;
    float mrow[2] = { -1e30f, -1e30f }, lrow_s[2] = { 0.f, 0.f };

    const int nch = tq + 1;
    for (int c = 0; c < nch; c++) {
        const int s0 = c * 64;

        float S[8][4];
#pragma unroll
        for (int i = 0; i < 8; i++)
#pragma unroll
            for (int j = 0; j < 4; j++) S[i][j] = 0.f;

#pragma unroll
        for (int k16 = 0; k16 < 8; k16++) {
#pragma unroll
            for (int nt2 = 0; nt2 < 4; nt2++) {
                const uint32_t bo = (nt2 * 16 + lrow) * FA_ROW + k16 * 32 + lcol16;
                uint32_t bh4[4], bl4[4];
                ldsm4(bh4, sKh + bo);
                ldsm4(bl4, sKl + bo);
                uint32_t bhe[2] = { bh4[0], bh4[2] }, bho[2] = { bh4[1], bh4[3] };
                uint32_t ble[2] = { bl4[0], bl4[2] }, blo[2] = { bl4[1], bl4[3] };
                mma_bf16(S[2 * nt2],     qfh[k16], bhe);
                mma_bf16(S[2 * nt2],     qfh[k16], ble);
                mma_bf16(S[2 * nt2],     qfl[k16], bhe);
                mma_bf16(S[2 * nt2 + 1], qfh[k16], bho);
                mma_bf16(S[2 * nt2 + 1], qfh[k16], blo);
                mma_bf16(S[2 * nt2 + 1], qfl[k16], bho);
            }
        }

        if (c == tq) {
#pragma unroll
            for (int nt = 0; nt < 8; nt++)
#pragma unroll
                for (int ci = 0; ci < 4; ci++) {
                    const int s = s0 + nt * 8 + 2 * tt + (ci & 1);
                    const int qr = qbase + w * 16 + gg + 8 * (ci >> 1);
                    if (s > qr) S[nt][ci] = -1e30f;
                }
        }

        float mnew[2];
#pragma unroll
        for (int r = 0; r < 2; r++) {
            float mx = mrow[r];
#pragma unroll
            for (int nt = 0; nt < 8; nt++)
                mx = fmaxf(mx, fmaxf(S[nt][2 * r], S[nt][2 * r + 1]));
            mx = fmaxf(mx, __shfl_xor_sync(0xffffffffu, mx, 1));
            mx = fmaxf(mx, __shfl_xor_sync(0xffffffffu, mx, 2));
            mnew[r] = mx;
            const float alpha = __expf(mrow[r] - mx);
            lrow_s[r] *= alpha;
            mrow[r] = mx;
#pragma unroll
            for (int dt = 0; dt < 16; dt++) {
                O[dt][2 * r]     *= alpha;
                O[dt][2 * r + 1] *= alpha;
            }
        }

        uint32_t Ph[4][4], Pl[4][4];
        float sum0 = 0.f, sum1 = 0.f;
#pragma unroll
        for (int ci16 = 0; ci16 < 4; ci16++) {
#pragma unroll
            for (int half = 0; half < 2; half++) {
                const int nt = 2 * ci16 + half;
                float p0 = __expf(S[nt][0] - mnew[0]);
                float p1 = __expf(S[nt][1] - mnew[0]);
                float p2 = __expf(S[nt][2] - mnew[1]);
                float p3 = __expf(S[nt][3] - mnew[1]);
                sum0 += p0 + p1;
                sum1 += p2 + p3;
                float h0 = __bfloat162float(__float2bfloat16(p0));
                float h1 = __bfloat162float(__float2bfloat16(p1));
                float h2 = __bfloat162float(__float2bfloat16(p2));
                float h3 = __bfloat162float(__float2bfloat16(p3));
                Ph[ci16][0 + 2 * half] = packbf(h0, h1);
                Ph[ci16][1 + 2 * half] = packbf(h2, h3);
                Pl[ci16][0 + 2 * half] = packbf(p0 - h0, p1 - h1);
                Pl[ci16][1 + 2 * half] = packbf(p2 - h2, p3 - h3);
            }
        }
        sum0 += __shfl_xor_sync(0xffffffffu, sum0, 1);
        sum0 += __shfl_xor_sync(0xffffffffu, sum0, 2);
        sum1 += __shfl_xor_sync(0xffffffffu, sum1, 1);
        sum1 += __shfl_xor_sync(0xffffffffu, sum1, 2);
        lrow_s[0] += sum0;
        lrow_s[1] += sum1;

        __syncthreads();
        if (c + 1 < nch) { loadK(s0 + 64); cp_wait<1>(); }
        else             { cp_wait<0>(); }
        __syncthreads();

#pragma unroll
        for (int dt2 = 0; dt2 < 8; dt2++) {
#pragma unroll
            for (int ci16 = 0; ci16 < 4; ci16++) {
                const uint32_t vo = (ci16 * 16 + lrow) * FA_ROW + dt2 * 32 + lcol16;
                uint32_t vfh[4], vfl[4];
                ldsm4t(vfh, sVh + vo);
                ldsm4t(vfl, sVl + vo);
                uint32_t vhe[2] = { vfh[0], vfh[1] }, vho[2] = { vfh[2], vfh[3] };
                uint32_t vle[2] = { vfl[0], vfl[1] }, vlo[2] = { vfl[2], vfl[3] };
                mma_bf16(O[2 * dt2],     Ph[ci16], vhe);
                mma_bf16(O[2 * dt2],     Pl[ci16], vhe);
                mma_bf16(O[2 * dt2],     Ph[ci16], vle);
                mma_bf16(O[2 * dt2 + 1], Ph[ci16], vho);
                mma_bf16(O[2 * dt2 + 1], Pl[ci16], vho);
                mma_bf16(O[2 * dt2 + 1], Ph[ci16], vlo);
            }
        }

        __syncthreads();
        if (c + 1 < nch) {
            loadV(s0 + 64);
            cp_wait<1>();
            __syncthreads();
        }
    }

    const float inv0 = 1.f / lrow_s[0], inv1 = 1.f / lrow_s[1];
    const int q0 = qbase + w * 16 + gg;
#pragma unroll
    for (int dt = 0; dt < 16; dt++) {
        const int col = dt * 8 + 2 * tt;
        const size_t o0 = (((size_t)b * T_ + q0) * H_ + h) * D_ + col;
        const size_t o1 = (((size_t)b * T_ + q0 + 8) * H_ + h) * D_ + col;
        float a0 = O[dt][0] * inv0, a1 = O[dt][1] * inv0;
        float a2 = O[dt][2] * inv1, a3 = O[dt][3] * inv1;
        float h0 = __bfloat162float(__float2bfloat16(a0));
        float h1 = __bfloat162float(__float2bfloat16(a1));
        float h2 = __bfloat162float(__float2bfloat16(a2));
        float h3 = __bfloat162float(__float2bfloat16(a3));
        *(uint32_t*)(oh + o0) = packbf(h0, h1);
        *(uint32_t*)(oh + o1) = packbf(h2, h3);
        *(uint32_t*)(ol + o0) = packbf(a0 - h0, a1 - h1);
        *(uint32_t*)(ol + o1) = packbf(a2 - h2, a3 - h3);
    }
}

// ---------------------------------------------------------------------------
extern "C" void kernel_launch(void* const* d_in, const int* in_sizes, int n_in,
                              void* d_out, int out_size)
{
    const float* x  = (const float*)d_in[0];
    const float* Wq = (const float*)d_in[1];
    const float* Wk = (const float*)d_in[2];
    const float* Wv = (const float*)d_in[3];
    const float* Wo = (const float*)d_in[4];
    const float* bo = (const float*)d_in[5];
    float* out = (float*)d_out;

    __nv_bfloat16 *xh, *xl, *ath, *atl, *qh, *ql, *kh, *kl, *vh, *vl;
    __nv_bfloat16 *wqh, *wql, *wkh, *wkl, *wvh, *wvl, *woh, *wol;
    cudaGetSymbolAddress((void**)&xh,  g_xh);
    cudaGetSymbolAddress((void**)&xl,  g_xl);
    cudaGetSymbolAddress((void**)&ath, g_ath);
    cudaGetSymbolAddress((void**)&atl, g_atl);
    cudaGetSymbolAddress((void**)&qh,  g_qh);
    cudaGetSymbolAddress((void**)&ql,  g_ql);
    cudaGetSymbolAddress((void**)&kh,  g_kh);
    cudaGetSymbolAddress((void**)&kl,  g_kl);
    cudaGetSymbolAddress((void**)&vh,  g_vh);
    cudaGetSymbolAddress((void**)&vl,  g_vl);
    cudaGetSymbolAddress((void**)&wqh, g_wqh);
    cudaGetSymbolAddress((void**)&wql, g_wql);
    cudaGetSymbolAddress((void**)&wkh, g_wkh);
    cudaGetSymbolAddress((void**)&wkl, g_wkl);
    cudaGetSymbolAddress((void**)&wvh, g_wvh);
    cudaGetSymbolAddress((void**)&wvl, g_wvl);
    cudaGetSymbolAddress((void**)&woh, g_woh);
    cudaGetSymbolAddress((void**)&wol, g_wol);

    cudaFuncSetAttribute(qkv_gemm_kernel,
                         cudaFuncAttributeMaxDynamicSharedMemorySize, GEMM_SMEM);
    cudaFuncSetAttribute(gemm_mma_kernel,
                         cudaFuncAttributeMaxDynamicSharedMemorySize, GEMM_SMEM);
    cudaFuncSetAttribute(flash_attn_kernel,
                         cudaFuncAttributeMaxDynamicSharedMemorySize, FA_SMEM);

    // preprocessing
    split_kernel<<<(M_ * C_ + 255) / 256, 256>>>(x, xh, xl, M_ * C_);
    transpose_split_all_kernel<<<40960, dim3(32, 8)>>>(
        Wq, Wk, Wv, Wo, wqh, wql, wkh, wkl, wvh, wvl, woh, wol);

    // fused QKV projection + RoPE + scale + bf16 split (256x128 tiles)
    qkv_gemm_kernel<<<dim3(48, M_ / 256), 256, GEMM_SMEM>>>(
        xh, xl, wqh, wql, wkh, wkl, wvh, wvl, qh, ql, kh, kl, vh, vl);

    // flash attention (bf16 hi/lo in and out)
    flash_attn_kernel<<<dim3(T_ / 64, H_, B_), 128, FA_SMEM>>>(
        qh, ql, kh, kl, vh, vl, ath, atl);

    // output projection + bias (256x128 tiles)
    gemm_mma_kernel<<<dim3(C_ / 128, M_ / 256), 256, GEMM_SMEM>>>(
        ath, atl, woh, wol, bo, out, C_, H_ * D_);
}

// round 14
// speedup vs baseline: 1.1880x; 1.1880x over previous
#include <cuda_runtime.h>
#include <cuda_bf16.h>
#include <math.h>
#include <stdint.h>

#define B_  2
#define T_  1024
#define C_  4096
#define H_  32
#define G_  8
#define D_  128
#define M_  (B_*T_)          // 2048 rows

// ---------------- scratch (__device__ globals; no allocs allowed) ----------
__device__ __nv_bfloat16 g_xh [M_ * C_];
__device__ __nv_bfloat16 g_xl [M_ * C_];
__device__ __nv_bfloat16 g_ath[M_ * C_];
__device__ __nv_bfloat16 g_atl[M_ * C_];
__device__ __nv_bfloat16 g_qh [M_ * H_ * D_];
__device__ __nv_bfloat16 g_ql [M_ * H_ * D_];
__device__ __nv_bfloat16 g_kh [M_ * G_ * D_];
__device__ __nv_bfloat16 g_kl [M_ * G_ * D_];
__device__ __nv_bfloat16 g_vh [M_ * G_ * D_];
__device__ __nv_bfloat16 g_vl [M_ * G_ * D_];
// transposed weights, [N, K] K-major, bf16 hi/lo
__device__ __nv_bfloat16 g_wqh[(H_*D_) * C_];
__device__ __nv_bfloat16 g_wql[(H_*D_) * C_];
__device__ __nv_bfloat16 g_wkh[(G_*D_) * C_];
__device__ __nv_bfloat16 g_wkl[(G_*D_) * C_];
__device__ __nv_bfloat16 g_wvh[(G_*D_) * C_];
__device__ __nv_bfloat16 g_wvl[(G_*D_) * C_];
__device__ __nv_bfloat16 g_woh[C_ * (H_*D_)];
__device__ __nv_bfloat16 g_wol[C_ * (H_*D_)];

// ---------------- helpers ---------------------------------------------------
__device__ __forceinline__ uint32_t smem_u32(const void* p) {
    uint32_t a;
    asm("{ .reg .u64 t; cvta.to.shared.u64 t, %1; cvt.u32.u64 %0, t; }"
        : "=r"(a) : "l"(p));
    return a;
}
__device__ __forceinline__ void cp16(uint32_t dst, const void* src) {
    asm volatile("cp.async.cg.shared.global [%0], [%1], 16;"
                 :: "r"(dst), "l"(src) : "memory");
}
__device__ __forceinline__ void cp_commit() {
    asm volatile("cp.async.commit_group;" ::: "memory");
}
template <int N>
__device__ __forceinline__ void cp_wait() {
    asm volatile("cp.async.wait_group %0;" :: "n"(N) : "memory");
}
__device__ __forceinline__ void mma_bf16(float* c, const uint32_t* a, const uint32_t* b) {
    asm volatile(
        "mma.sync.aligned.m16n8k16.row.col.f32.bf16.bf16.f32 "
        "{%0,%1,%2,%3}, {%4,%5,%6,%7}, {%8,%9}, {%0,%1,%2,%3};"
        : "+f"(c[0]), "+f"(c[1]), "+f"(c[2]), "+f"(c[3])
        : "r"(a[0]), "r"(a[1]), "r"(a[2]), "r"(a[3]), "r"(b[0]), "r"(b[1]));
}
__device__ __forceinline__ void ldsm4(uint32_t* r, uint32_t a) {
    asm volatile("ldmatrix.sync.aligned.m8n8.x4.shared.b16 {%0,%1,%2,%3}, [%4];"
        : "=r"(r[0]), "=r"(r[1]), "=r"(r[2]), "=r"(r[3]) : "r"(a));
}
__device__ __forceinline__ void ldsm4t(uint32_t* r, uint32_t a) {
    asm volatile("ldmatrix.sync.aligned.m8n8.x4.trans.shared.b16 {%0,%1,%2,%3}, [%4];"
        : "=r"(r[0]), "=r"(r[1]), "=r"(r[2]), "=r"(r[3]) : "r"(a));
}
__device__ __forceinline__ uint32_t packbf(float a, float b) {
    __nv_bfloat162 t;
    t.x = __float2bfloat16(a);
    t.y = __float2bfloat16(b);
    return *(uint32_t*)&t;
}

// ---------------- GEMM tile config: 128x128, BK=32, XOR-swizzled smem ------
// Row = 32 bf16 = 64 B = 4 chunks of 16 B. chunk' = chunk ^ ((row>>1)&3).
// Conflict-free for cp.async 16B stores and ldmatrix 16-row reads.
#define MAT_BYTES 8192                    // 128 rows * 64 B
#define STAGE_BYTES (4 * MAT_BYTES)       // Ah, Al, Bh, Bl = 32768
#define NSTAGE 3
#define GEMM_SMEM (NSTAGE * STAGE_BYTES)  // 98304

// per-stage cp.async: 2048 16B chunks, 8 per thread (256 threads)
#define GEMM_ISSUE_STAGE_BODY                                                  \
    const int k0 = c << 5;                                                     \
    _Pragma("unroll")                                                          \
    for (int j = 0; j < 8; j++) {                                              \
        const int mat = j >> 1;                                                \
        const int idx = tid + ((j & 1) << 8);      /* 0..511 */                \
        const int r   = idx >> 2;                                              \
        const int s   = idx & 3;                                               \
        const int grow = (mat < 2) ? (m0 + r) : (n0 + r);                      \
        const __nv_bfloat16* gp = (mat == 0) ? Ahp : (mat == 1) ? Alp          \
                                : (mat == 2) ? Bhp : Blp;                      \
        const __nv_bfloat16* src = gp + (size_t)grow * Kdim + k0 + s * 8;      \
        const uint32_t dst = smb + st * STAGE_BYTES + mat * MAT_BYTES          \
                           + r * 64 + ((s ^ ((r >> 1) & 3)) << 4);             \
        cp16(dst, src);                                                        \
    }                                                                          \
    cp_commit();

// 3-stage mainloop; warp tile 32(m) x 64(n); acc[2][8][4]
#define GEMM_MAINLOOP(ACC)                                                     \
    issue_stage(0, 0);                                                         \
    if (nchunks > 1) issue_stage(1, 1);                                        \
    for (int c = 0; c < nchunks; ++c) {                                        \
        const int st = c % NSTAGE;                                             \
        if (c + 2 < nchunks) { issue_stage(c + 2, (c + 2) % NSTAGE); cp_wait<2>(); } \
        else if (c + 1 < nchunks) cp_wait<1>();                                \
        else cp_wait<0>();                                                     \
        __syncthreads();                                                       \
        const uint32_t sAh = smb + st * STAGE_BYTES;                           \
        const uint32_t sAl = sAh + MAT_BYTES;                                  \
        const uint32_t sBh = sAh + 2 * MAT_BYTES;                              \
        const uint32_t sBl = sAh + 3 * MAT_BYTES;                              \
        _Pragma("unroll")                                                      \
        for (int k16 = 0; k16 < 32; k16 += 16) {                               \
            const uint32_t ch = (uint32_t)((((k16 >> 3) + colsel) ^ swz) << 4);\
            uint32_t ah[2][4], al[2][4];                                       \
            _Pragma("unroll")                                                  \
            for (int mt = 0; mt < 2; mt++) {                                   \
                const uint32_t ao = aoff0 + mt * 16 * 64 + ch;                 \
                ldsm4(ah[mt], sAh + ao);                                       \
                ldsm4(al[mt], sAl + ao);                                       \
            }                                                                  \
            _Pragma("unroll")                                                  \
            for (int nt2 = 0; nt2 < 4; nt2++) {                                \
                const uint32_t bo = boff0 + nt2 * 16 * 64 + ch;                \
                uint32_t bh4[4], bl4[4];                                       \
                ldsm4(bh4, sBh + bo);                                          \
                ldsm4(bl4, sBl + bo);                                          \
                uint32_t bhe[2] = { bh4[0], bh4[2] }, bho[2] = { bh4[1], bh4[3] }; \
                uint32_t ble[2] = { bl4[0], bl4[2] }, blo[2] = { bl4[1], bl4[3] }; \
                _Pragma("unroll")                                              \
                for (int mt = 0; mt < 2; mt++) {                               \
                    mma_bf16(ACC[mt][2 * nt2],     ah[mt], bhe);               \
                    mma_bf16(ACC[mt][2 * nt2],     ah[mt], ble);               \
                    mma_bf16(ACC[mt][2 * nt2],     al[mt], bhe);               \
                    mma_bf16(ACC[mt][2 * nt2 + 1], ah[mt], bho);               \
                    mma_bf16(ACC[mt][2 * nt2 + 1], ah[mt], blo);               \
                    mma_bf16(ACC[mt][2 * nt2 + 1], al[mt], bho);               \
                }                                                              \
            }                                                                  \
        }                                                                      \
        __syncthreads();                                                       \
    }

// ---------------------------------------------------------------------------
// Fused QKV projection GEMM (128x128 tiles) + RoPE/scale/split epilogue.
// grid.x in [0,48): [0,32) Q, [32,40) K, [40,48) V; grid.y = M/128.
// ---------------------------------------------------------------------------
__global__ __launch_bounds__(256, 2)
void qkv_gemm_kernel(const __nv_bfloat16* __restrict__ xh_, const __nv_bfloat16* __restrict__ xl_,
                     const __nv_bfloat16* __restrict__ wqh_, const __nv_bfloat16* __restrict__ wql_,
                     const __nv_bfloat16* __restrict__ wkh_, const __nv_bfloat16* __restrict__ wkl_,
                     const __nv_bfloat16* __restrict__ wvh_, const __nv_bfloat16* __restrict__ wvl_,
                     __nv_bfloat16* __restrict__ qh_, __nv_bfloat16* __restrict__ ql_,
                     __nv_bfloat16* __restrict__ kh_, __nv_bfloat16* __restrict__ kl_,
                     __nv_bfloat16* __restrict__ vh_, __nv_bfloat16* __restrict__ vl_)
{
    extern __shared__ char sm[];
    const uint32_t smb = smem_u32(sm);
    const int tid  = threadIdx.x;
    const int lane = tid & 31;
    const int w    = tid >> 5;
    const int wm   = w & 3;
    const int wn   = w >> 2;
    const int gg   = lane >> 2;
    const int tt   = lane & 3;
    const int m0   = blockIdx.y * 128;
    const int bx   = blockIdx.x;

    const __nv_bfloat16 *Bhp, *Blp;
    __nv_bfloat16 *OH, *OL;
    int n0, Nmat, rope;
    float scale;
    if (bx < 32)      { Bhp = wqh_; Blp = wql_; OH = qh_; OL = ql_; n0 = bx * 128;        Nmat = H_ * D_; rope = 1; scale = 0.08838834764831845f; }
    else if (bx < 40) { Bhp = wkh_; Blp = wkl_; OH = kh_; OL = kl_; n0 = (bx - 32) * 128; Nmat = G_ * D_; rope = 1; scale = 1.f; }
    else              { Bhp = wvh_; Blp = wvl_; OH = vh_; OL = vl_; n0 = (bx - 40) * 128; Nmat = G_ * D_; rope = 0; scale = 1.f; }

    const __nv_bfloat16* Ahp = xh_;
    const __nv_bfloat16* Alp = xl_;
    const int Kdim = C_;
    const int nchunks = Kdim >> 5;

    auto issue_stage = [&](int c, int st) { GEMM_ISSUE_STAGE_BODY };

    float acc[2][8][4];
#pragma unroll
    for (int i = 0; i < 2; i++)
#pragma unroll
        for (int j = 0; j < 8; j++)
#pragma unroll
            for (int l = 0; l < 4; l++) acc[i][j][l] = 0.f;

    const uint32_t lrow  = (lane & 7) + ((lane >> 3) & 1) * 8;
    const int colsel = (lane >> 4) & 1;
    const int swz    = (int)((lrow >> 1) & 3);
    const uint32_t aoff0 = (wm * 32 + lrow) * 64;
    const uint32_t boff0 = (wn * 64 + lrow) * 64;

    GEMM_MAINLOOP(acc)

    // ---- fused epilogue: RoPE + scale + bf16 hi/lo split ----
#pragma unroll
    for (int mt = 0; mt < 2; mt++) {
#pragma unroll
        for (int nt = 0; nt < 8; nt++) {
            const int row = m0 + wm * 32 + mt * 16 + gg;
            const int col = n0 + wn * 64 + nt * 8 + 2 * tt;
            float a0 = acc[mt][nt][0], a1 = acc[mt][nt][1];
            float a2 = acc[mt][nt][2], a3 = acc[mt][nt][3];
            if (rope) {
                const int d2 = (col & 127) >> 1;
                const float invf = powf(10000.0f, -(float)d2 / 64.0f);
                float s0, c0, s1, c1;
                sincosf((float)(row & (T_ - 1)) * invf, &s0, &c0);
                sincosf((float)((row + 8) & (T_ - 1)) * invf, &s1, &c1);
                const float r0 = (a0 * c0 - a1 * s0) * scale;
                const float i0 = (a0 * s0 + a1 * c0) * scale;
                const float r1 = (a2 * c1 - a3 * s1) * scale;
                const float i1 = (a2 * s1 + a3 * c1) * scale;
                a0 = r0; a1 = i0; a2 = r1; a3 = i1;
            }
            const float h0 = __bfloat162float(__float2bfloat16(a0));
            const float h1 = __bfloat162float(__float2bfloat16(a1));
            const float h2 = __bfloat162float(__float2bfloat16(a2));
            const float h3 = __bfloat162float(__float2bfloat16(a3));
            const size_t o0 = (size_t)row * Nmat + col;
            const size_t o1 = (size_t)(row + 8) * Nmat + col;
            *(uint32_t*)(OH + o0) = packbf(h0, h1);
            *(uint32_t*)(OH + o1) = packbf(h2, h3);
            *(uint32_t*)(OL + o0) = packbf(a0 - h0, a1 - h1);
            *(uint32_t*)(OL + o1) = packbf(a2 - h2, a3 - h3);
        }
    }
}

// ---------------------------------------------------------------------------
// O-projection GEMM (128x128 tiles), fp32 out + bias.
// ---------------------------------------------------------------------------
__global__ __launch_bounds__(256, 2)
void gemm_mma_kernel(const __nv_bfloat16* __restrict__ Ahp, const __nv_bfloat16* __restrict__ Alp,
                     const __nv_bfloat16* __restrict__ Bhp, const __nv_bfloat16* __restrict__ Blp,
                     const float* __restrict__ bias, float* __restrict__ Cm,
                     int Ndim, int Kdim)
{
    extern __shared__ char sm[];
    const uint32_t smb = smem_u32(sm);
    const int tid  = threadIdx.x;
    const int lane = tid & 31;
    const int w    = tid >> 5;
    const int wm   = w & 3;
    const int wn   = w >> 2;
    const int gg   = lane >> 2;
    const int tt   = lane & 3;
    const int m0   = blockIdx.y * 128;
    const int n0   = blockIdx.x * 128;

    const int nchunks = Kdim >> 5;

    auto issue_stage = [&](int c, int st) { GEMM_ISSUE_STAGE_BODY };

    float acc[2][8][4];
#pragma unroll
    for (int i = 0; i < 2; i++)
#pragma unroll
        for (int j = 0; j < 8; j++)
#pragma unroll
            for (int l = 0; l < 4; l++) acc[i][j][l] = 0.f;

    const uint32_t lrow  = (lane & 7) + ((lane >> 3) & 1) * 8;
    const int colsel = (lane >> 4) & 1;
    const int swz    = (int)((lrow >> 1) & 3);
    const uint32_t aoff0 = (wm * 32 + lrow) * 64;
    const uint32_t boff0 = (wn * 64 + lrow) * 64;

    GEMM_MAINLOOP(acc)

#pragma unroll
    for (int mt = 0; mt < 2; mt++) {
#pragma unroll
        for (int nt = 0; nt < 8; nt++) {
            const int row = m0 + wm * 32 + mt * 16 + gg;
            const int col = n0 + wn * 64 + nt * 8 + 2 * tt;
            float2 v0 = make_float2(acc[mt][nt][0] + bias[col], acc[mt][nt][1] + bias[col + 1]);
            float2 v1 = make_float2(acc[mt][nt][2] + bias[col], acc[mt][nt][3] + bias[col + 1]);
            *(float2*)(Cm + (size_t)row * Ndim + col)       = v0;
            *(float2*)(Cm + (size_t)(row + 8) * Ndim + col) = v1;
        }
    }
}

// ---------------- fp32 -> bf16 hi/lo split ---------------------------------
__global__ void split_kernel(const float* __restrict__ src,
                             __nv_bfloat16* __restrict__ hi,
                             __nv_bfloat16* __restrict__ lo, int n)
{
    int i = blockIdx.x * blockDim.x + threadIdx.x;
    if (i >= n) return;
    float a = src[i];
    __nv_bfloat16 h = __float2bfloat16(a);
    hi[i] = h;
    lo[i] = __float2bfloat16(a - __bfloat162float(h));
}

// ---------------------------------------------------------------------------
// Merged transpose+split of all 4 weight matrices (flat 1D tile grid).
// ---------------------------------------------------------------------------
__global__ void transpose_split_all_kernel(
    const float* __restrict__ Wq, const float* __restrict__ Wk,
    const float* __restrict__ Wv, const float* __restrict__ Wo,
    __nv_bfloat16* __restrict__ wqh, __nv_bfloat16* __restrict__ wql,
    __nv_bfloat16* __restrict__ wkh, __nv_bfloat16* __restrict__ wkl,
    __nv_bfloat16* __restrict__ wvh, __nv_bfloat16* __restrict__ wvl,
    __nv_bfloat16* __restrict__ woh, __nv_bfloat16* __restrict__ wol)
{
    __shared__ float t[32][33];
    const int tile = blockIdx.x;
    const float* W;
    __nv_bfloat16 *Th, *Tl;
    int Kd, Nd, l;
    if (tile < 16384)      { W = Wq; Th = wqh; Tl = wql; Kd = C_;      Nd = H_ * D_; l = tile; }
    else if (tile < 20480) { W = Wk; Th = wkh; Tl = wkl; Kd = C_;      Nd = G_ * D_; l = tile - 16384; }
    else if (tile < 24576) { W = Wv; Th = wvh; Tl = wvl; Kd = C_;      Nd = G_ * D_; l = tile - 20480; }
    else                   { W = Wo; Th = woh; Tl = wol; Kd = H_ * D_; Nd = C_;      l = tile - 24576; }
    const int nx = Nd >> 5;
    const int n0 = (l % nx) * 32, k0 = (l / nx) * 32;
    const int tx = threadIdx.x, ty = threadIdx.y;
#pragma unroll
    for (int j = 0; j < 32; j += 8)
        t[ty + j][tx] = W[(size_t)(k0 + ty + j) * Nd + n0 + tx];
    __syncthreads();
#pragma unroll
    for (int j = 0; j < 32; j += 8) {
        float a = t[tx][ty + j];
        __nv_bfloat16 h = __float2bfloat16(a);
        size_t o = (size_t)(n0 + ty + j) * Kd + k0 + tx;
        Th[o] = h;
        Tl[o] = __float2bfloat16(a - __bfloat162float(h));
    }
}

// ---------------------------------------------------------------------------
// Flash attention, bf16x3 HMMA (unchanged from R8).
// ---------------------------------------------------------------------------
#define FA_ROW 272
#define FA_MAT (64 * FA_ROW)
#define FA_SMEM (6 * FA_MAT)

__global__ __launch_bounds__(128, 2)
void flash_attn_kernel(const __nv_bfloat16* __restrict__ qh, const __nv_bfloat16* __restrict__ ql,
                       const __nv_bfloat16* __restrict__ kh, const __nv_bfloat16* __restrict__ kl,
                       const __nv_bfloat16* __restrict__ vh, const __nv_bfloat16* __restrict__ vl,
                       __nv_bfloat16* __restrict__ oh, __nv_bfloat16* __restrict__ ol)
{
    extern __shared__ char sm[];
    const uint32_t smb = smem_u32(sm);
    const uint32_t sQh = smb,            sQl = smb + FA_MAT;
    const uint32_t sKh = smb + 2*FA_MAT, sKl = smb + 3*FA_MAT;
    const uint32_t sVh = smb + 4*FA_MAT, sVl = smb + 5*FA_MAT;
    const int tid = threadIdx.x, lane = tid & 31, w = tid >> 5;
    const int gg = lane >> 2, tt = lane & 3;
    const int tq = blockIdx.x, h = blockIdx.y, b = blockIdx.z, g = h >> 2;
    const int qbase = tq * 64;

    const uint32_t lrow = (lane & 7) + ((lane >> 3) & 1) * 8;
    const uint32_t lcol16 = ((lane >> 4) & 1) * 16;

#pragma unroll
    for (int j = 0; j < 16; j++) {
        const int i = tid + j * 128;
        const int matlo = i >> 10, idx = i & 1023, r = idx >> 4, s = idx & 15;
        const __nv_bfloat16* src = (matlo ? ql : qh)
            + (((size_t)b * T_ + qbase + r) * H_ + h) * D_ + s * 8;
        cp16((matlo ? sQl : sQh) + r * FA_ROW + s * 16, src);
    }
    cp_commit();

    auto loadK = [&](int s0) {
#pragma unroll
        for (int j = 0; j < 16; j++) {
            const int i = tid + j * 128;
            const int matlo = i >> 10, idx = i & 1023, r = idx >> 4, s = idx & 15;
            const __nv_bfloat16* src = (matlo ? kl : kh)
                + (((size_t)b * T_ + s0 + r) * G_ + g) * D_ + s * 8;
            cp16((matlo ? sKl : sKh) + r * FA_ROW + s * 16, src);
        }
        cp_commit();
    };
    auto loadV = [&](int s0) {
#pragma unroll
        for (int j = 0; j < 16; j++) {
            const int i = tid + j * 128;
            const int matlo = i >> 10, idx = i & 1023, r = idx >> 4, s = idx & 15;
            const __nv_bfloat16* src = (matlo ? vl : vh)
                + (((size_t)b * T_ + s0 + r) * G_ + g) * D_ + s * 8;
            cp16((matlo ? sVl : sVh) + r * FA_ROW + s * 16, src);
        }
        cp_commit();
    };

    loadK(0);
    loadV(0);
    cp_wait<1>();
    __syncthreads();

    uint32_t qfh[8][4], qfl[8][4];
    const uint32_t qoff = (w * 16 + lrow) * FA_ROW + lcol16;
#pragma unroll
    for (int k16 = 0; k16 < 8; k16++) {
        ldsm4(qfh[k16], sQh + qoff + k16 * 32);
        ldsm4(qfl[k16], sQl + qoff + k16 * 32);
    }

    float O[16][4];
#pragma unroll
    for (int i = 0; i < 16; i++)
#pragma unroll
        for (int j = 0; j < 4; j++) O[i][j] = 0.f;
    float mrow[2] = { -1e30f, -1e30f }, lrow_s[2] = { 0.f, 0.f };

    const int nch = tq + 1;
    for (int c = 0; c < nch; c++) {
        const int s0 = c * 64;

        float S[8][4];
#pragma unroll
        for (int i = 0; i < 8; i++)
#pragma unroll
            for (int j = 0; j < 4; j++) S[i][j] = 0.f;

#pragma unroll
        for (int k16 = 0; k16 < 8; k16++) {
#pragma unroll
            for (int nt2 = 0; nt2 < 4; nt2++) {
                const uint32_t bo = (nt2 * 16 + lrow) * FA_ROW + k16 * 32 + lcol16;
                uint32_t bh4[4], bl4[4];
                ldsm4(bh4, sKh + bo);
                ldsm4(bl4, sKl + bo);
                uint32_t bhe[2] = { bh4[0], bh4[2] }, bho[2] = { bh4[1], bh4[3] };
                uint32_t ble[2] = { bl4[0], bl4[2] }, blo[2] = { bl4[1], bl4[3] };
                mma_bf16(S[2 * nt2],     qfh[k16], bhe);
                mma_bf16(S[2 * nt2],     qfh[k16], ble);
                mma_bf16(S[2 * nt2],     qfl[k16], bhe);
                mma_bf16(S[2 * nt2 + 1], qfh[k16], bho);
                mma_bf16(S[2 * nt2 + 1], qfh[k16], blo);
                mma_bf16(S[2 * nt2 + 1], qfl[k16], bho);
            }
        }

        if (c == tq) {
#pragma unroll
            for (int nt = 0; nt < 8; nt++)
#pragma unroll
                for (int ci = 0; ci < 4; ci++) {
                    const int s = s0 + nt * 8 + 2 * tt + (ci & 1);
                    const int qr = qbase + w * 16 + gg + 8 * (ci >> 1);
                    if (s > qr) S[nt][ci] = -1e30f;
                }
        }

        float mnew[2];
#pragma unroll
        for (int r = 0; r < 2; r++) {
            float mx = mrow[r];
#pragma unroll
            for (int nt = 0; nt < 8; nt++)
                mx = fmaxf(mx, fmaxf(S[nt][2 * r], S[nt][2 * r + 1]));
            mx = fmaxf(mx, __shfl_xor_sync(0xffffffffu, mx, 1));
            mx = fmaxf(mx, __shfl_xor_sync(0xffffffffu, mx, 2));
            mnew[r] = mx;
            const float alpha = __expf(mrow[r] - mx);
            lrow_s[r] *= alpha;
            mrow[r] = mx;
#pragma unroll
            for (int dt = 0; dt < 16; dt++) {
                O[dt][2 * r]     *= alpha;
                O[dt][2 * r + 1] *= alpha;
            }
        }

        uint32_t Ph[4][4], Pl[4][4];
        float sum0 = 0.f, sum1 = 0.f;
#pragma unroll
        for (int ci16 = 0; ci16 < 4; ci16++) {
#pragma unroll
            for (int half = 0; half < 2; half++) {
                const int nt = 2 * ci16 + half;
                float p0 = __expf(S[nt][0] - mnew[0]);
                float p1 = __expf(S[nt][1] - mnew[0]);
                float p2 = __expf(S[nt][2] - mnew[1]);
                float p3 = __expf(S[nt][3] - mnew[1]);
                sum0 += p0 + p1;
                sum1 += p2 + p3;
                float h0 = __bfloat162float(__float2bfloat16(p0));
                float h1 = __bfloat162float(__float2bfloat16(p1));
                float h2 = __bfloat162float(__float2bfloat16(p2));
                float h3 = __bfloat162float(__float2bfloat16(p3));
                Ph[ci16][0 + 2 * half] = packbf(h0, h1);
                Ph[ci16][1 + 2 * half] = packbf(h2, h3);
                Pl[ci16][0 + 2 * half] = packbf(p0 - h0, p1 - h1);
                Pl[ci16][1 + 2 * half] = packbf(p2 - h2, p3 - h3);
            }
        }
        sum0 += __shfl_xor_sync(0xffffffffu, sum0, 1);
        sum0 += __shfl_xor_sync(0xffffffffu, sum0, 2);
        sum1 += __shfl_xor_sync(0xffffffffu, sum1, 1);
        sum1 += __shfl_xor_sync(0xffffffffu, sum1, 2);
        lrow_s[0] += sum0;
        lrow_s[1] += sum1;

        __syncthreads();
        if (c + 1 < nch) { loadK(s0 + 64); cp_wait<1>(); }
        else             { cp_wait<0>(); }
        __syncthreads();

#pragma unroll
        for (int dt2 = 0; dt2 < 8; dt2++) {
#pragma unroll
            for (int ci16 = 0; ci16 < 4; ci16++) {
                const uint32_t vo = (ci16 * 16 + lrow) * FA_ROW + dt2 * 32 + lcol16;
                uint32_t vfh[4], vfl[4];
                ldsm4t(vfh, sVh + vo);
                ldsm4t(vfl, sVl + vo);
                uint32_t vhe[2] = { vfh[0], vfh[1] }, vho[2] = { vfh[2], vfh[3] };
                uint32_t vle[2] = { vfl[0], vfl[1] }, vlo[2] = { vfl[2], vfl[3] };
                mma_bf16(O[2 * dt2],     Ph[ci16], vhe);
                mma_bf16(O[2 * dt2],     Pl[ci16], vhe);
                mma_bf16(O[2 * dt2],     Ph[ci16], vle);
                mma_bf16(O[2 * dt2 + 1], Ph[ci16], vho);
                mma_bf16(O[2 * dt2 + 1], Pl[ci16], vho);
                mma_bf16(O[2 * dt2 + 1], Ph[ci16], vlo);
            }
        }

        __syncthreads();
        if (c + 1 < nch) {
            loadV(s0 + 64);
            cp_wait<1>();
            __syncthreads();
        }
    }

    const float inv0 = 1.f / lrow_s[0], inv1 = 1.f / lrow_s[1];
    const int q0 = qbase + w * 16 + gg;
#pragma unroll
    for (int dt = 0; dt < 16; dt++) {
        const int col = dt * 8 + 2 * tt;
        const size_t o0 = (((size_t)b * T_ + q0) * H_ + h) * D_ + col;
        const size_t o1 = (((size_t)b * T_ + q0 + 8) * H_ + h) * D_ + col;
        float a0 = O[dt][0] * inv0, a1 = O[dt][1] * inv0;
        float a2 = O[dt][2] * inv1, a3 = O[dt][3] * inv1;
        float h0 = __bfloat162float(__float2bfloat16(a0));
        float h1 = __bfloat162float(__float2bfloat16(a1));
        float h2 = __bfloat162float(__float2bfloat16(a2));
        float h3 = __bfloat162float(__float2bfloat16(a3));
        *(uint32_t*)(oh + o0) = packbf(h0, h1);
        *(uint32_t*)(oh + o1) = packbf(h2, h3);
        *(uint32_t*)(ol + o0) = packbf(a0 - h0, a1 - h1);
        *(uint32_t*)(ol + o1) = packbf(a2 - h2, a3 - h3);
    }
}

// ---------------------------------------------------------------------------
extern "C" void kernel_launch(void* const* d_in, const int* in_sizes, int n_in,
                              void* d_out, int out_size)
{
    const float* x  = (const float*)d_in[0];
    const float* Wq = (const float*)d_in[1];
    const float* Wk = (const float*)d_in[2];
    const float* Wv = (const float*)d_in[3];
    const float* Wo = (const float*)d_in[4];
    const float* bo = (const float*)d_in[5];
    float* out = (float*)d_out;

    __nv_bfloat16 *xh, *xl, *ath, *atl, *qh, *ql, *kh, *kl, *vh, *vl;
    __nv_bfloat16 *wqh, *wql, *wkh, *wkl, *wvh, *wvl, *woh, *wol;
    cudaGetSymbolAddress((void**)&xh,  g_xh);
    cudaGetSymbolAddress((void**)&xl,  g_xl);
    cudaGetSymbolAddress((void**)&ath, g_ath);
    cudaGetSymbolAddress((void**)&atl, g_atl);
    cudaGetSymbolAddress((void**)&qh,  g_qh);
    cudaGetSymbolAddress((void**)&ql,  g_ql);
    cudaGetSymbolAddress((void**)&kh,  g_kh);
    cudaGetSymbolAddress((void**)&kl,  g_kl);
    cudaGetSymbolAddress((void**)&vh,  g_vh);
    cudaGetSymbolAddress((void**)&vl,  g_vl);
    cudaGetSymbolAddress((void**)&wqh, g_wqh);
    cudaGetSymbolAddress((void**)&wql, g_wql);
    cudaGetSymbolAddress((void**)&wkh, g_wkh);
    cudaGetSymbolAddress((void**)&wkl, g_wkl);
    cudaGetSymbolAddress((void**)&wvh, g_wvh);
    cudaGetSymbolAddress((void**)&wvl, g_wvl);
    cudaGetSymbolAddress((void**)&woh, g_woh);
    cudaGetSymbolAddress((void**)&wol, g_wol);

    cudaFuncSetAttribute(qkv_gemm_kernel,
                         cudaFuncAttributeMaxDynamicSharedMemorySize, GEMM_SMEM);
    cudaFuncSetAttribute(gemm_mma_kernel,
                         cudaFuncAttributeMaxDynamicSharedMemorySize, GEMM_SMEM);
    cudaFuncSetAttribute(flash_attn_kernel,
                         cudaFuncAttributeMaxDynamicSharedMemorySize, FA_SMEM);

    // preprocessing
    split_kernel<<<(M_ * C_ + 255) / 256, 256>>>(x, xh, xl, M_ * C_);
    transpose_split_all_kernel<<<40960, dim3(32, 8)>>>(
        Wq, Wk, Wv, Wo, wqh, wql, wkh, wkl, wvh, wvl, woh, wol);

    // fused QKV projection + RoPE + scale + bf16 split (128x128 tiles, 3-stage)
    qkv_gemm_kernel<<<dim3(48, M_ / 128), 256, GEMM_SMEM>>>(
        xh, xl, wqh, wql, wkh, wkl, wvh, wvl, qh, ql, kh, kl, vh, vl);

    // flash attention (bf16 hi/lo in and out)
    flash_attn_kernel<<<dim3(T_ / 64, H_, B_), 128, FA_SMEM>>>(
        qh, ql, kh, kl, vh, vl, ath, atl);

    // output projection + bias (128x128 tiles, 3-stage)
    gemm_mma_kernel<<<dim3(C_ / 128, M_ / 128), 256, GEMM_SMEM>>>(
        ath, atl, woh, wol, bo, out, C_, H_ * D_);
}

// round 16
// speedup vs baseline: 1.2064x; 1.0155x over previous
#include <cuda_runtime.h>
#include <cuda_bf16.h>
#include <math.h>
#include <stdint.h>

#define B_  2
#define T_  1024
#define C_  4096
#define H_  32
#define G_  8
#define D_  128
#define M_  (B_*T_)          // 2048 rows

// ---------------- scratch (__device__ globals; no allocs allowed) ----------
__device__ __nv_bfloat16 g_xh [M_ * C_];
__device__ __nv_bfloat16 g_xl [M_ * C_];
__device__ __nv_bfloat16 g_ath[M_ * C_];
__device__ __nv_bfloat16 g_atl[M_ * C_];
__device__ __nv_bfloat16 g_qh [M_ * H_ * D_];
__device__ __nv_bfloat16 g_ql [M_ * H_ * D_];
__device__ __nv_bfloat16 g_kh [M_ * G_ * D_];
__device__ __nv_bfloat16 g_kl [M_ * G_ * D_];
__device__ __nv_bfloat16 g_vh [M_ * G_ * D_];
__device__ __nv_bfloat16 g_vl [M_ * G_ * D_];
// transposed weights, [N, K] K-major, bf16 hi/lo
__device__ __nv_bfloat16 g_wqh[(H_*D_) * C_];
__device__ __nv_bfloat16 g_wql[(H_*D_) * C_];
__device__ __nv_bfloat16 g_wkh[(G_*D_) * C_];
__device__ __nv_bfloat16 g_wkl[(G_*D_) * C_];
__device__ __nv_bfloat16 g_wvh[(G_*D_) * C_];
__device__ __nv_bfloat16 g_wvl[(G_*D_) * C_];
__device__ __nv_bfloat16 g_woh[C_ * (H_*D_)];
__device__ __nv_bfloat16 g_wol[C_ * (H_*D_)];

// ---------------- helpers ---------------------------------------------------
__device__ __forceinline__ uint32_t smem_u32(const void* p) {
    uint32_t a;
    asm("{ .reg .u64 t; cvta.to.shared.u64 t, %1; cvt.u32.u64 %0, t; }"
        : "=r"(a) : "l"(p));
    return a;
}
__device__ __forceinline__ void cp16(uint32_t dst, const void* src) {
    asm volatile("cp.async.cg.shared.global [%0], [%1], 16;"
                 :: "r"(dst), "l"(src) : "memory");
}
__device__ __forceinline__ void cp_commit() {
    asm volatile("cp.async.commit_group;" ::: "memory");
}
template <int N>
__device__ __forceinline__ void cp_wait() {
    asm volatile("cp.async.wait_group %0;" :: "n"(N) : "memory");
}
__device__ __forceinline__ void mma_bf16(float* c, const uint32_t* a, const uint32_t* b) {
    asm volatile(
        "mma.sync.aligned.m16n8k16.row.col.f32.bf16.bf16.f32 "
        "{%0,%1,%2,%3}, {%4,%5,%6,%7}, {%8,%9}, {%0,%1,%2,%3};"
        : "+f"(c[0]), "+f"(c[1]), "+f"(c[2]), "+f"(c[3])
        : "r"(a[0]), "r"(a[1]), "r"(a[2]), "r"(a[3]), "r"(b[0]), "r"(b[1]));
}
__device__ __forceinline__ void ldsm4(uint32_t* r, uint32_t a) {
    asm volatile("ldmatrix.sync.aligned.m8n8.x4.shared.b16 {%0,%1,%2,%3}, [%4];"
        : "=r"(r[0]), "=r"(r[1]), "=r"(r[2]), "=r"(r[3]) : "r"(a));
}
__device__ __forceinline__ void ldsm4t(uint32_t* r, uint32_t a) {
    asm volatile("ldmatrix.sync.aligned.m8n8.x4.trans.shared.b16 {%0,%1,%2,%3}, [%4];"
        : "=r"(r[0]), "=r"(r[1]), "=r"(r[2]), "=r"(r[3]) : "r"(a));
}
__device__ __forceinline__ uint32_t packbf(float a, float b) {
    __nv_bfloat162 t;
    t.x = __float2bfloat16(a);
    t.y = __float2bfloat16(b);
    return *(uint32_t*)&t;
}

// ---------------- GEMM tile config: 128x128, BK=32, XOR-swizzled smem ------
#define MAT_BYTES 8192                    // 128 rows * 64 B
#define STAGE_BYTES (4 * MAT_BYTES)       // Ah, Al, Bh, Bl = 32768
#define NSTAGE 3
#define GEMM_SMEM (NSTAGE * STAGE_BYTES)  // 98304

// per-stage cp.async: 2048 16B chunks, 8 per thread (256 threads)
#define GEMM_ISSUE_STAGE_BODY                                                  \
    const int k0 = c << 5;                                                     \
    _Pragma("unroll")                                                          \
    for (int j = 0; j < 8; j++) {                                              \
        const int mat = j >> 1;                                                \
        const int idx = tid + ((j & 1) << 8);      /* 0..511 */                \
        const int r   = idx >> 2;                                              \
        const int s   = idx & 3;                                               \
        const int grow = (mat < 2) ? (m0 + r) : (n0 + r);                      \
        const __nv_bfloat16* gp = (mat == 0) ? Ahp : (mat == 1) ? Alp          \
                                : (mat == 2) ? Bhp : Blp;                      \
        const __nv_bfloat16* src = gp + (size_t)grow * Kdim + k0 + s * 8;      \
        const uint32_t dst = smb + st * STAGE_BYTES + mat * MAT_BYTES          \
                           + r * 64 + ((s ^ ((r >> 1) & 3)) << 4);             \
        cp16(dst, src);                                                        \
    }                                                                          \
    cp_commit();

// 3-stage mainloop, ONE __syncthreads per chunk, MMA RAW distance 4.
#define GEMM_MAINLOOP(ACC)                                                     \
    issue_stage(0, 0);                                                         \
    if (nchunks > 1) issue_stage(1, 1);                                        \
    for (int c = 0; c < nchunks; ++c) {                                        \
        const int st = c % NSTAGE;                                             \
        if (c + 1 < nchunks) cp_wait<1>(); else cp_wait<0>();                  \
        __syncthreads();                                                       \
        if (c + 2 < nchunks) issue_stage(c + 2, (c + 2) % NSTAGE);             \
        const uint32_t sAh = smb + st * STAGE_BYTES;                           \
        const uint32_t sAl = sAh + MAT_BYTES;                                  \
        const uint32_t sBh = sAh + 2 * MAT_BYTES;                              \
        const uint32_t sBl = sAh + 3 * MAT_BYTES;                              \
        _Pragma("unroll")                                                      \
        for (int k16 = 0; k16 < 32; k16 += 16) {                               \
            const uint32_t ch = (uint32_t)((((k16 >> 3) + colsel) ^ swz) << 4);\
            uint32_t ah[2][4], al[2][4];                                       \
            _Pragma("unroll")                                                  \
            for (int mt = 0; mt < 2; mt++) {                                   \
                const uint32_t ao = aoff0 + mt * 16 * 64 + ch;                 \
                ldsm4(ah[mt], sAh + ao);                                       \
                ldsm4(al[mt], sAl + ao);                                       \
            }                                                                  \
            _Pragma("unroll")                                                  \
            for (int nt2 = 0; nt2 < 4; nt2++) {                                \
                const uint32_t bo = boff0 + nt2 * 16 * 64 + ch;                \
                uint32_t bh4[4], bl4[4];                                       \
                ldsm4(bh4, sBh + bo);                                          \
                ldsm4(bl4, sBl + bo);                                          \
                uint32_t bhe[2] = { bh4[0], bh4[2] }, bho[2] = { bh4[1], bh4[3] }; \
                uint32_t ble[2] = { bl4[0], bl4[2] }, blo[2] = { bl4[1], bl4[3] }; \
                mma_bf16(ACC[0][2 * nt2],     ah[0], bhe);                     \
                mma_bf16(ACC[0][2 * nt2 + 1], ah[0], bho);                     \
                mma_bf16(ACC[1][2 * nt2],     ah[1], bhe);                     \
                mma_bf16(ACC[1][2 * nt2 + 1], ah[1], bho);                     \
                mma_bf16(ACC[0][2 * nt2],     ah[0], ble);                     \
                mma_bf16(ACC[0][2 * nt2 + 1], ah[0], blo);                     \
                mma_bf16(ACC[1][2 * nt2],     ah[1], ble);                     \
                mma_bf16(ACC[1][2 * nt2 + 1], ah[1], blo);                     \
                mma_bf16(ACC[0][2 * nt2],     al[0], bhe);                     \
                mma_bf16(ACC[0][2 * nt2 + 1], al[0], bho);                     \
                mma_bf16(ACC[1][2 * nt2],     al[1], bhe);                     \
                mma_bf16(ACC[1][2 * nt2 + 1], al[1], bho);                     \
            }                                                                  \
        }                                                                      \
    }                                                                          \
    __syncthreads();

// ---------------------------------------------------------------------------
// Fused QKV projection GEMM (128x128 tiles) + RoPE/scale/split epilogue.
// ---------------------------------------------------------------------------
__global__ __launch_bounds__(256, 2)
void qkv_gemm_kernel(const __nv_bfloat16* __restrict__ xh_, const __nv_bfloat16* __restrict__ xl_,
                     const __nv_bfloat16* __restrict__ wqh_, const __nv_bfloat16* __restrict__ wql_,
                     const __nv_bfloat16* __restrict__ wkh_, const __nv_bfloat16* __restrict__ wkl_,
                     const __nv_bfloat16* __restrict__ wvh_, const __nv_bfloat16* __restrict__ wvl_,
                     __nv_bfloat16* __restrict__ qh_, __nv_bfloat16* __restrict__ ql_,
                     __nv_bfloat16* __restrict__ kh_, __nv_bfloat16* __restrict__ kl_,
                     __nv_bfloat16* __restrict__ vh_, __nv_bfloat16* __restrict__ vl_)
{
    extern __shared__ char sm[];
    const uint32_t smb = smem_u32(sm);
    const int tid  = threadIdx.x;
    const int lane = tid & 31;
    const int w    = tid >> 5;
    const int wm   = w & 3;
    const int wn   = w >> 2;
    const int gg   = lane >> 2;
    const int tt   = lane & 3;
    const int m0   = blockIdx.y * 128;
    const int bx   = blockIdx.x;

    const __nv_bfloat16 *Bhp, *Blp;
    __nv_bfloat16 *OH, *OL;
    int n0, Nmat, rope;
    float scale;
    if (bx < 32)      { Bhp = wqh_; Blp = wql_; OH = qh_; OL = ql_; n0 = bx * 128;        Nmat = H_ * D_; rope = 1; scale = 0.08838834764831845f; }
    else if (bx < 40) { Bhp = wkh_; Blp = wkl_; OH = kh_; OL = kl_; n0 = (bx - 32) * 128; Nmat = G_ * D_; rope = 1; scale = 1.f; }
    else              { Bhp = wvh_; Blp = wvl_; OH = vh_; OL = vl_; n0 = (bx - 40) * 128; Nmat = G_ * D_; rope = 0; scale = 1.f; }

    const __nv_bfloat16* Ahp = xh_;
    const __nv_bfloat16* Alp = xl_;
    const int Kdim = C_;
    const int nchunks = Kdim >> 5;

    auto issue_stage = [&](int c, int st) { GEMM_ISSUE_STAGE_BODY };

    float acc[2][8][4];
#pragma unroll
    for (int i = 0; i < 2; i++)
#pragma unroll
        for (int j = 0; j < 8; j++)
#pragma unroll
            for (int l = 0; l < 4; l++) acc[i][j][l] = 0.f;

    const uint32_t lrow  = (lane & 7) + ((lane >> 3) & 1) * 8;
    const int colsel = (lane >> 4) & 1;
    const int swz    = (int)((lrow >> 1) & 3);
    const uint32_t aoff0 = (wm * 32 + lrow) * 64;
    const uint32_t boff0 = (wn * 64 + lrow) * 64;

    GEMM_MAINLOOP(acc)

    // ---- fused epilogue: RoPE + scale + bf16 hi/lo split ----
#pragma unroll
    for (int mt = 0; mt < 2; mt++) {
#pragma unroll
        for (int nt = 0; nt < 8; nt++) {
            const int row = m0 + wm * 32 + mt * 16 + gg;
            const int col = n0 + wn * 64 + nt * 8 + 2 * tt;
            float a0 = acc[mt][nt][0], a1 = acc[mt][nt][1];
            float a2 = acc[mt][nt][2], a3 = acc[mt][nt][3];
            if (rope) {
                const int d2 = (col & 127) >> 1;
                const float invf = powf(10000.0f, -(float)d2 / 64.0f);
                float s0, c0, s1, c1;
                sincosf((float)(row & (T_ - 1)) * invf, &s0, &c0);
                sincosf((float)((row + 8) & (T_ - 1)) * invf, &s1, &c1);
                const float r0 = (a0 * c0 - a1 * s0) * scale;
                const float i0 = (a0 * s0 + a1 * c0) * scale;
                const float r1 = (a2 * c1 - a3 * s1) * scale;
                const float i1 = (a2 * s1 + a3 * c1) * scale;
                a0 = r0; a1 = i0; a2 = r1; a3 = i1;
            }
            const float h0 = __bfloat162float(__float2bfloat16(a0));
            const float h1 = __bfloat162float(__float2bfloat16(a1));
            const float h2 = __bfloat162float(__float2bfloat16(a2));
            const float h3 = __bfloat162float(__float2bfloat16(a3));
            const size_t o0 = (size_t)row * Nmat + col;
            const size_t o1 = (size_t)(row + 8) * Nmat + col;
            *(uint32_t*)(OH + o0) = packbf(h0, h1);
            *(uint32_t*)(OH + o1) = packbf(h2, h3);
            *(uint32_t*)(OL + o0) = packbf(a0 - h0, a1 - h1);
            *(uint32_t*)(OL + o1) = packbf(a2 - h2, a3 - h3);
        }
    }
}

// ---------------------------------------------------------------------------
// O-projection GEMM (128x128 tiles), fp32 out + bias.
// ---------------------------------------------------------------------------
__global__ __launch_bounds__(256, 2)
void gemm_mma_kernel(const __nv_bfloat16* __restrict__ Ahp, const __nv_bfloat16* __restrict__ Alp,
                     const __nv_bfloat16* __restrict__ Bhp, const __nv_bfloat16* __restrict__ Blp,
                     const float* __restrict__ bias, float* __restrict__ Cm,
                     int Ndim, int Kdim)
{
    extern __shared__ char sm[];
    const uint32_t smb = smem_u32(sm);
    const int tid  = threadIdx.x;
    const int lane = tid & 31;
    const int w    = tid >> 5;
    const int wm   = w & 3;
    const int wn   = w >> 2;
    const int gg   = lane >> 2;
    const int tt   = lane & 3;
    const int m0   = blockIdx.y * 128;
    const int n0   = blockIdx.x * 128;

    const int nchunks = Kdim >> 5;

    auto issue_stage = [&](int c, int st) { GEMM_ISSUE_STAGE_BODY };

    float acc[2][8][4];
#pragma unroll
    for (int i = 0; i < 2; i++)
#pragma unroll
        for (int j = 0; j < 8; j++)
#pragma unroll
            for (int l = 0; l < 4; l++) acc[i][j][l] = 0.f;

    const uint32_t lrow  = (lane & 7) + ((lane >> 3) & 1) * 8;
    const int colsel = (lane >> 4) & 1;
    const int swz    = (int)((lrow >> 1) & 3);
    const uint32_t aoff0 = (wm * 32 + lrow) * 64;
    const uint32_t boff0 = (wn * 64 + lrow) * 64;

    GEMM_MAINLOOP(acc)

#pragma unroll
    for (int mt = 0; mt < 2; mt++) {
#pragma unroll
        for (int nt = 0; nt < 8; nt++) {
            const int row = m0 + wm * 32 + mt * 16 + gg;
            const int col = n0 + wn * 64 + nt * 8 + 2 * tt;
            float2 v0 = make_float2(acc[mt][nt][0] + bias[col], acc[mt][nt][1] + bias[col + 1]);
            float2 v1 = make_float2(acc[mt][nt][2] + bias[col], acc[mt][nt][3] + bias[col + 1]);
            *(float2*)(Cm + (size_t)row * Ndim + col)       = v0;
            *(float2*)(Cm + (size_t)(row + 8) * Ndim + col) = v1;
        }
    }
}

// ---------------------------------------------------------------------------
// Merged preprocessing: transpose+split of 4 weights + pass-through split of x.
// Tiles: Wq 16384 | Wk 4096 | Wv 4096 | Wo 16384 | x 8192  (total 49152)
// ---------------------------------------------------------------------------
__global__ void prep_all_kernel(
    const float* __restrict__ x,
    const float* __restrict__ Wq, const float* __restrict__ Wk,
    const float* __restrict__ Wv, const float* __restrict__ Wo,
    __nv_bfloat16* __restrict__ xh,  __nv_bfloat16* __restrict__ xl,
    __nv_bfloat16* __restrict__ wqh, __nv_bfloat16* __restrict__ wql,
    __nv_bfloat16* __restrict__ wkh, __nv_bfloat16* __restrict__ wkl,
    __nv_bfloat16* __restrict__ wvh, __nv_bfloat16* __restrict__ wvl,
    __nv_bfloat16* __restrict__ woh, __nv_bfloat16* __restrict__ wol)
{
    __shared__ float t[32][33];
    const int tile = blockIdx.x;
    const int tx = threadIdx.x, ty = threadIdx.y;

    if (tile >= 40960) {                 // x split, no transpose
        const int l  = tile - 40960;     // 64 x 128 tiles of 32x32
        const int r0 = (l >> 7) * 32, c0 = (l & 127) * 32;
#pragma unroll
        for (int j = 0; j < 32; j += 8) {
            const size_t idx = (size_t)(r0 + ty + j) * C_ + c0 + tx;
            const float a = x[idx];
            const __nv_bfloat16 h = __float2bfloat16(a);
            xh[idx] = h;
            xl[idx] = __float2bfloat16(a - __bfloat162float(h));
        }
        return;
    }

    const float* W;
    __nv_bfloat16 *Th, *Tl;
    int Kd, Nd, l;
    if (tile < 16384)      { W = Wq; Th = wqh; Tl = wql; Kd = C_;      Nd = H_ * D_; l = tile; }
    else if (tile < 20480) { W = Wk; Th = wkh; Tl = wkl; Kd = C_;      Nd = G_ * D_; l = tile - 16384; }
    else if (tile < 24576) { W = Wv; Th = wvh; Tl = wvl; Kd = C_;      Nd = G_ * D_; l = tile - 20480; }
    else                   { W = Wo; Th = woh; Tl = wol; Kd = H_ * D_; Nd = C_;      l = tile - 24576; }
    const int nx = Nd >> 5;
    const int n0 = (l % nx) * 32, k0 = (l / nx) * 32;
#pragma unroll
    for (int j = 0; j < 32; j += 8)
        t[ty + j][tx] = W[(size_t)(k0 + ty + j) * Nd + n0 + tx];
    __syncthreads();
#pragma unroll
    for (int j = 0; j < 32; j += 8) {
        float a = t[tx][ty + j];
        __nv_bfloat16 h = __float2bfloat16(a);
        size_t o = (size_t)(n0 + ty + j) * Kd + k0 + tx;
        Th[o] = h;
        Tl[o] = __float2bfloat16(a - __bfloat162float(h));
    }
}

// ---------------------------------------------------------------------------
// Flash attention, bf16x3 HMMA; MMA loops interleaved (RAW distance 2).
// ---------------------------------------------------------------------------
#define FA_ROW 272
#define FA_MAT (64 * FA_ROW)
#define FA_SMEM (6 * FA_MAT)

__global__ __launch_bounds__(128, 2)
void flash_attn_kernel(const __nv_bfloat16* __restrict__ qh, const __nv_bfloat16* __restrict__ ql,
                       const __nv_bfloat16* __restrict__ kh, const __nv_bfloat16* __restrict__ kl,
                       const __nv_bfloat16* __restrict__ vh, const __nv_bfloat16* __restrict__ vl,
                       __nv_bfloat16* __restrict__ oh, __nv_bfloat16* __restrict__ ol)
{
    extern __shared__ char sm[];
    const uint32_t smb = smem_u32(sm);
    const uint32_t sQh = smb,            sQl = smb + FA_MAT;
    const uint32_t sKh = smb + 2*FA_MAT, sKl = smb + 3*FA_MAT;
    const uint32_t sVh = smb + 4*FA_MAT, sVl = smb + 5*FA_MAT;
    const int tid = threadIdx.x, lane = tid & 31, w = tid >> 5;
    const int gg = lane >> 2, tt = lane & 3;
    const int tq = blockIdx.x, h = blockIdx.y, b = blockIdx.z, g = h >> 2;
    const int qbase = tq * 64;

    const uint32_t lrow = (lane & 7) + ((lane >> 3) & 1) * 8;
    const uint32_t lcol16 = ((lane >> 4) & 1) * 16;

#pragma unroll
    for (int j = 0; j < 16; j++) {
        const int i = tid + j * 128;
        const int matlo = i >> 10, idx = i & 1023, r = idx >> 4, s = idx & 15;
        const __nv_bfloat16* src = (matlo ? ql : qh)
            + (((size_t)b * T_ + qbase + r) * H_ + h) * D_ + s * 8;
        cp16((matlo ? sQl : sQh) + r * FA_ROW + s * 16, src);
    }
    cp_commit();

    auto loadK = [&](int s0) {
#pragma unroll
        for (int j = 0; j < 16; j++) {
            const int i = tid + j * 128;
            const int matlo = i >> 10, idx = i & 1023, r = idx >> 4, s = idx & 15;
            const __nv_bfloat16* src = (matlo ? kl : kh)
                + (((size_t)b * T_ + s0 + r) * G_ + g) * D_ + s * 8;
            cp16((matlo ? sKl : sKh) + r * FA_ROW + s * 16, src);
        }
        cp_commit();
    };
    auto loadV = [&](int s0) {
#pragma unroll
        for (int j = 0; j < 16; j++) {
            const int i = tid + j * 128;
            const int matlo = i >> 10, idx = i & 1023, r = idx >> 4, s = idx & 15;
            const __nv_bfloat16* src = (matlo ? vl : vh)
                + (((size_t)b * T_ + s0 + r) * G_ + g) * D_ + s * 8;
            cp16((matlo ? sVl : sVh) + r * FA_ROW + s * 16, src);
        }
        cp_commit();
    };

    loadK(0);
    loadV(0);
    cp_wait<1>();
    __syncthreads();

    uint32_t qfh[8][4], qfl[8][4];
    const uint32_t qoff = (w * 16 + lrow) * FA_ROW + lcol16;
#pragma unroll
    for (int k16 = 0; k16 < 8; k16++) {
        ldsm4(qfh[k16], sQh + qoff + k16 * 32);
        ldsm4(qfl[k16], sQl + qoff + k16 * 32);
    }

    float O[16][4];
#pragma unroll
    for (int i = 0; i < 16; i++)
#pragma unroll
        for (int j = 0; j < 4; j++) O[i][j] = 0.f;
    float mrow[2] = { -1e30f, -1e30f }, lrow_s[2] = { 0.f, 0.f };

    const int nch = tq + 1;
    for (int c = 0; c < nch; c++) {
        const int s0 = c * 64;

        float S[8][4];
#pragma unroll
        for (int i = 0; i < 8; i++)
#pragma unroll
            for (int j = 0; j < 4; j++) S[i][j] = 0.f;

#pragma unroll
        for (int k16 = 0; k16 < 8; k16++) {
#pragma unroll
            for (int nt2 = 0; nt2 < 4; nt2++) {
                const uint32_t bo = (nt2 * 16 + lrow) * FA_ROW + k16 * 32 + lcol16;
                uint32_t bh4[4], bl4[4];
                ldsm4(bh4, sKh + bo);
                ldsm4(bl4, sKl + bo);
                uint32_t bhe[2] = { bh4[0], bh4[2] }, bho[2] = { bh4[1], bh4[3] };
                uint32_t ble[2] = { bl4[0], bl4[2] }, blo[2] = { bl4[1], bl4[3] };
                mma_bf16(S[2 * nt2],     qfh[k16], bhe);
                mma_bf16(S[2 * nt2 + 1], qfh[k16], bho);
                mma_bf16(S[2 * nt2],     qfh[k16], ble);
                mma_bf16(S[2 * nt2 + 1], qfh[k16], blo);
                mma_bf16(S[2 * nt2],     qfl[k16], bhe);
                mma_bf16(S[2 * nt2 + 1], qfl[k16], bho);
            }
        }

        if (c == tq) {
#pragma unroll
            for (int nt = 0; nt < 8; nt++)
#pragma unroll
                for (int ci = 0; ci < 4; ci++) {
                    const int s = s0 + nt * 8 + 2 * tt + (ci & 1);
                    const int qr = qbase + w * 16 + gg + 8 * (ci >> 1);
                    if (s > qr) S[nt][ci] = -1e30f;
                }
        }

        float mnew[2];
#pragma unroll
        for (int r = 0; r < 2; r++) {
            float mx = mrow[r];
#pragma unroll
            for (int nt = 0; nt < 8; nt++)
                mx = fmaxf(mx, fmaxf(S[nt][2 * r], S[nt][2 * r + 1]));
            mx = fmaxf(mx, __shfl_xor_sync(0xffffffffu, mx, 1));
            mx = fmaxf(mx, __shfl_xor_sync(0xffffffffu, mx, 2));
            mnew[r] = mx;
            const float alpha = __expf(mrow[r] - mx);
            lrow_s[r] *= alpha;
            mrow[r] = mx;
#pragma unroll
            for (int dt = 0; dt < 16; dt++) {
                O[dt][2 * r]     *= alpha;
                O[dt][2 * r + 1] *= alpha;
            }
        }

        uint32_t Ph[4][4], Pl[4][4];
        float sum0 = 0.f, sum1 = 0.f;
#pragma unroll
        for (int ci16 = 0; ci16 < 4; ci16++) {
#pragma unroll
            for (int half = 0; half < 2; half++) {
                const int nt = 2 * ci16 + half;
                float p0 = __expf(S[nt][0] - mnew[0]);
                float p1 = __expf(S[nt][1] - mnew[0]);
                float p2 = __expf(S[nt][2] - mnew[1]);
                float p3 = __expf(S[nt][3] - mnew[1]);
                sum0 += p0 + p1;
                sum1 += p2 + p3;
                float h0 = __bfloat162float(__float2bfloat16(p0));
                float h1 = __bfloat162float(__float2bfloat16(p1));
                float h2 = __bfloat162float(__float2bfloat16(p2));
                float h3 = __bfloat162float(__float2bfloat16(p3));
                Ph[ci16][0 + 2 * half] = packbf(h0, h1);
                Ph[ci16][1 + 2 * half] = packbf(h2, h3);
                Pl[ci16][0 + 2 * half] = packbf(p0 - h0, p1 - h1);
                Pl[ci16][1 + 2 * half] = packbf(p2 - h2, p3 - h3);
            }
        }
        sum0 += __shfl_xor_sync(0xffffffffu, sum0, 1);
        sum0 += __shfl_xor_sync(0xffffffffu, sum0, 2);
        sum1 += __shfl_xor_sync(0xffffffffu, sum1, 1);
        sum1 += __shfl_xor_sync(0xffffffffu, sum1, 2);
        lrow_s[0] += sum0;
        lrow_s[1] += sum1;

        __syncthreads();
        if (c + 1 < nch) { loadK(s0 + 64); cp_wait<1>(); }
        else             { cp_wait<0>(); }
        __syncthreads();

#pragma unroll
        for (int dt2 = 0; dt2 < 8; dt2++) {
#pragma unroll
            for (int ci16 = 0; ci16 < 4; ci16++) {
                const uint32_t vo = (ci16 * 16 + lrow) * FA_ROW + dt2 * 32 + lcol16;
                uint32_t vfh[4], vfl[4];
                ldsm4t(vfh, sVh + vo);
                ldsm4t(vfl, sVl + vo);
                uint32_t vhe[2] = { vfh[0], vfh[1] }, vho[2] = { vfh[2], vfh[3] };
                uint32_t vle[2] = { vfl[0], vfl[1] }, vlo[2] = { vfl[2], vfl[3] };
                mma_bf16(O[2 * dt2],     Ph[ci16], vhe);
                mma_bf16(O[2 * dt2 + 1], Ph[ci16], vho);
                mma_bf16(O[2 * dt2],     Pl[ci16], vhe);
                mma_bf16(O[2 * dt2 + 1], Pl[ci16], vho);
                mma_bf16(O[2 * dt2],     Ph[ci16], vle);
                mma_bf16(O[2 * dt2 + 1], Ph[ci16], vlo);
            }
        }

        __syncthreads();
        if (c + 1 < nch) {
            loadV(s0 + 64);
            cp_wait<1>();
            __syncthreads();
        }
    }

    const float inv0 = 1.f / lrow_s[0], inv1 = 1.f / lrow_s[1];
    const int q0 = qbase + w * 16 + gg;
#pragma unroll
    for (int dt = 0; dt < 16; dt++) {
        const int col = dt * 8 + 2 * tt;
        const size_t o0 = (((size_t)b * T_ + q0) * H_ + h) * D_ + col;
        const size_t o1 = (((size_t)b * T_ + q0 + 8) * H_ + h) * D_ + col;
        float a0 = O[dt][0] * inv0, a1 = O[dt][1] * inv0;
        float a2 = O[dt][2] * inv1, a3 = O[dt][3] * inv1;
        float h0 = __bfloat162float(__float2bfloat16(a0));
        float h1 = __bfloat162float(__float2bfloat16(a1));
        float h2 = __bfloat162float(__float2bfloat16(a2));
        float h3 = __bfloat162float(__float2bfloat16(a3));
        *(uint32_t*)(oh + o0) = packbf(h0, h1);
        *(uint32_t*)(oh + o1) = packbf(h2, h3);
        *(uint32_t*)(ol + o0) = packbf(a0 - h0, a1 - h1);
        *(uint32_t*)(ol + o1) = packbf(a2 - h2, a3 - h3);
    }
}

// ---------------------------------------------------------------------------
extern "C" void kernel_launch(void* const* d_in, const int* in_sizes, int n_in,
                              void* d_out, int out_size)
{
    const float* x  = (const float*)d_in[0];
    const float* Wq = (const float*)d_in[1];
    const float* Wk = (const float*)d_in[2];
    const float* Wv = (const float*)d_in[3];
    const float* Wo = (const float*)d_in[4];
    const float* bo = (const float*)d_in[5];
    float* out = (float*)d_out;

    __nv_bfloat16 *xh, *xl, *ath, *atl, *qh, *ql, *kh, *kl, *vh, *vl;
    __nv_bfloat16 *wqh, *wql, *wkh, *wkl, *wvh, *wvl, *woh, *wol;
    cudaGetSymbolAddress((void**)&xh,  g_xh);
    cudaGetSymbolAddress((void**)&xl,  g_xl);
    cudaGetSymbolAddress((void**)&ath, g_ath);
    cudaGetSymbolAddress((void**)&atl, g_atl);
    cudaGetSymbolAddress((void**)&qh,  g_qh);
    cudaGetSymbolAddress((void**)&ql,  g_ql);
    cudaGetSymbolAddress((void**)&kh,  g_kh);
    cudaGetSymbolAddress((void**)&kl,  g_kl);
    cudaGetSymbolAddress((void**)&vh,  g_vh);
    cudaGetSymbolAddress((void**)&vl,  g_vl);
    cudaGetSymbolAddress((void**)&wqh, g_wqh);
    cudaGetSymbolAddress((void**)&wql, g_wql);
    cudaGetSymbolAddress((void**)&wkh, g_wkh);
    cudaGetSymbolAddress((void**)&wkl, g_wkl);
    cudaGetSymbolAddress((void**)&wvh, g_wvh);
    cudaGetSymbolAddress((void**)&wvl, g_wvl);
    cudaGetSymbolAddress((void**)&woh, g_woh);
    cudaGetSymbolAddress((void**)&wol, g_wol);

    cudaFuncSetAttribute(qkv_gemm_kernel,
                         cudaFuncAttributeMaxDynamicSharedMemorySize, GEMM_SMEM);
    cudaFuncSetAttribute(gemm_mma_kernel,
                         cudaFuncAttributeMaxDynamicSharedMemorySize, GEMM_SMEM);
    cudaFuncSetAttribute(flash_attn_kernel,
                         cudaFuncAttributeMaxDynamicSharedMemorySize, FA_SMEM);

    // single preprocessing launch: weight transpose+split + x split
    prep_all_kernel<<<49152, dim3(32, 8)>>>(
        x, Wq, Wk, Wv, Wo, xh, xl,
        wqh, wql, wkh, wkl, wvh, wvl, woh, wol);

    // fused QKV projection + RoPE + scale + bf16 split
    qkv_gemm_kernel<<<dim3(48, M_ / 128), 256, GEMM_SMEM>>>(
        xh, xl, wqh, wql, wkh, wkl, wvh, wvl, qh, ql, kh, kl, vh, vl);

    // flash attention (bf16 hi/lo in and out)
    flash_attn_kernel<<<dim3(T_ / 64, H_, B_), 128, FA_SMEM>>>(
        qh, ql, kh, kl, vh, vl, ath, atl);

    // output projection + bias
    gemm_mma_kernel<<<dim3(C_ / 128, M_ / 128), 256, GEMM_SMEM>>>(
        ath, atl, woh, wol, bo, out, C_, H_ * D_);
}